// round 15
// baseline (speedup 1.0000x reference)
#include <cuda_runtime.h>

#define MAX_B        1024
#define MAGS_PER_TF  9
#define THREADS      128
#define VPT          6       // 128*6*49 = 37632 exact
#define NWARPS       (THREADS / 32)
#define MEAN_CHUNKS_F 4      // front reducer blocks per image (fused path)

// Persistent device state, zero-initialized at module load. All counters are
// monotonic across graph replays — no reset kernel is ever needed.
__device__ unsigned int          g_mdone[MAX_B];  // reducer-block completions
__device__ unsigned int          g_acnt[MAX_B];   // apply-block epoch counter
__device__ float                 g_sum[MAX_B];    // running sum (reset via atomicExch)
__device__ volatile unsigned int g_flag[MAX_B];   // published epoch number
__device__ volatile float        g_mean[MAX_B];   // published mean

// Generic (non-exact-tiling) fallback path scratch:
#define MEAN_CHUNKS_G 32
__device__ float g_part[MAX_B * MEAN_CHUNKS_G];

// ---------------------------------------------------------------------------
__device__ __forceinline__ float block_reduce(float val)
{
    #pragma unroll
    for (int off = 16; off > 0; off >>= 1)
        val += __shfl_xor_sync(0xFFFFFFFFu, val, off);

    __shared__ float ws[NWARPS];
    const int lane = threadIdx.x & 31;
    const int wid  = threadIdx.x >> 5;
    if (lane == 0) ws[wid] = val;
    __syncthreads();

    float v = 0.0f;
    if (wid == 0) {
        v = (lane < NWARPS) ? ws[lane] : 0.0f;
        #pragma unroll
        for (int off = 2; off > 0; off >>= 1)
            v += __shfl_xor_sync(0xFFFFFFFFu, v, off);
    }
    return v;  // valid in warp 0
}

// ---------------------------------------------------------------------------
// Fused kernel (128-thread / VPT-6 apply tiles). Grid layout:
//   [0, B*MEAN_CHUNKS_F)        front reducer blocks (contrast images only)
//   [front, front + B*bpi)      apply blocks, bpi per image, exact tiling
// Front blocks run first (in-order CTA placement): apply blocks for contrast
// images normally find the mean already published — no spin in practice.
// ---------------------------------------------------------------------------
__global__ void __launch_bounds__(THREADS)
fused_kernel(const float4* __restrict__ x,
             const int* __restrict__ sample,
             const int* __restrict__ apply_mask,
             float4* __restrict__ out,
             int blocks_per_img,
             int vec_per_img,
             int B)
{
    const int front = B * MEAN_CHUNKS_F;
    const float inv_n = 1.0f / (float)(vec_per_img * 4);

    if (blockIdx.x < front) {
        // ================= front reducer block =================
        const int b     = blockIdx.x / MEAN_CHUNKS_F;
        const int chunk = blockIdx.x - b * MEAN_CHUNKS_F;

        const int s  = __ldg(&sample[b]);
        const int tf = s / MAGS_PER_TF;
        if (!((tf == 1) && (__ldg(&apply_mask[s]) > 0))) return;  // no read

        const int chunk_vecs = vec_per_img / MEAN_CHUNKS_F;   // exact by launch check
        const unsigned int start = (unsigned int)b * vec_per_img + chunk * chunk_vecs;

        float acc = 0.0f;
        for (int i = threadIdx.x; i < chunk_vecs; i += THREADS) {
            float4 w = __ldg(&x[start + i]);   // cached: warm for the apply pass
            acc += (w.x + w.y) + (w.z + w.w);
        }
        float total = block_reduce(acc);

        if (threadIdx.x == 0) {
            atomicAdd(&g_sum[b], total);
            __threadfence();
            const unsigned int d = atomicAdd(&g_mdone[b], 1u) + 1u;
            if (d % (unsigned int)MEAN_CHUNKS_F == 0u) {
                float sum = atomicExch(&g_sum[b], 0.0f);
                g_mean[b] = sum * inv_n;
                __threadfence();
                g_flag[b] = d / (unsigned int)MEAN_CHUNKS_F;  // publish epoch
            }
        }
        return;
    }

    // ================= apply block =================
    const int abix = blockIdx.x - front;
    const int b    = abix / blocks_per_img;
    const int blk  = abix - b * blocks_per_img;

    const int s  = __ldg(&sample[b]);
    const int tf = s / MAGS_PER_TF;
    const float mag = (float)(s % MAGS_PER_TF + 1) * 0.1f;
    const bool applied  = (__ldg(&apply_mask[s]) > 0);
    const bool contrast = applied && (tf == 1);

    const unsigned int base = (unsigned int)b * (unsigned int)vec_per_img
                            + (unsigned int)blk * (THREADS * VPT)
                            + threadIdx.x;

    if (!contrast) {
        // ---------- slim streaming path (7/8 of blocks) ----------
        float alpha = 1.0f, beta = 0.0f;
        if (applied) {
            if (tf == 0)      { beta = mag; }                            // brightness
            else if (tf == 2) { alpha = 1.0f - 2.0f * mag; beta = mag; } // invert
            else              { alpha = 1.0f + mag; }                    // gain
        }

        float4 v[VPT];
        #pragma unroll
        for (int k = 0; k < VPT; k++)
            v[k] = __ldcs(&x[base + k * THREADS]);

        #pragma unroll
        for (int k = 0; k < VPT; k++) {
            v[k].x = __saturatef(fmaf(alpha, v[k].x, beta));
            v[k].y = __saturatef(fmaf(alpha, v[k].y, beta));
            v[k].z = __saturatef(fmaf(alpha, v[k].z, beta));
            v[k].w = __saturatef(fmaf(alpha, v[k].w, beta));
            __stcs(&out[base + k * THREADS], v[k]);
        }
        return;
    }

    // ---------- contrast path: mean normally already published ----------
    __shared__ float s_mean;
    __shared__ int   s_fallback;

    if (threadIdx.x == 0) {
        s_fallback = 0;
        const unsigned int d = atomicAdd(&g_acnt[b], 1u) + 1u;
        const unsigned int bp = (unsigned int)blocks_per_img;
        const unsigned int my_epoch = (d + bp - 1u) / bp;

        int spins = 0;
        while (g_flag[b] < my_epoch) {          // expected: already satisfied
            __nanosleep(40);
            if (++spins > 4000000) { s_fallback = 1; break; }
        }
        if (!s_fallback) {
            __threadfence();                     // acquire
            s_mean = g_mean[b];
        }
    }
    __syncthreads();

    if (s_fallback) {
        // Guaranteed forward progress (never expected): recompute locally.
        const float4* img = x + (size_t)b * vec_per_img;
        float a2 = 0.0f;
        for (int i = threadIdx.x; i < vec_per_img; i += THREADS) {
            float4 w = __ldg(&img[i]);
            a2 += (w.x + w.y) + (w.z + w.w);
        }
        __syncthreads();
        float t2 = block_reduce(a2);
        if (threadIdx.x == 0) s_mean = t2 * inv_n;
        __syncthreads();
    }

    const float alpha = 1.0f + mag;
    const float beta  = -s_mean * mag;

    // Single pass: data is L2-warm from the reducer blocks.
    float4 v[VPT];
    #pragma unroll
    for (int k = 0; k < VPT; k++)
        v[k] = __ldg(&x[base + k * THREADS]);

    #pragma unroll
    for (int k = 0; k < VPT; k++) {
        v[k].x = __saturatef(fmaf(alpha, v[k].x, beta));
        v[k].y = __saturatef(fmaf(alpha, v[k].y, beta));
        v[k].z = __saturatef(fmaf(alpha, v[k].z, beta));
        v[k].w = __saturatef(fmaf(alpha, v[k].w, beta));
        __stcs(&out[base + k * THREADS], v[k]);
    }
}

// ---------------------------------------------------------------------------
// Generic fallback (shapes without exact tiling): two-kernel scheme.
// ---------------------------------------------------------------------------
__global__ void mean_kernel(const float4* __restrict__ x,
                            const int* __restrict__ sample,
                            const int* __restrict__ apply_mask,
                            int vec_per_img)
{
    const int b     = blockIdx.x;
    const int chunk = blockIdx.y;

    const int s  = __ldg(&sample[b]);
    const int tf = s / MAGS_PER_TF;
    if (!((tf == 1) && (__ldg(&apply_mask[s]) > 0))) return;

    const int chunk_vecs = (vec_per_img + MEAN_CHUNKS_G - 1) / MEAN_CHUNKS_G;
    const int start = chunk * chunk_vecs;
    const int end   = min(start + chunk_vecs, vec_per_img);

    const float4* img = x + (size_t)b * vec_per_img;
    float acc = 0.0f;
    for (int i = start + threadIdx.x; i < end; i += blockDim.x) {
        float4 w = __ldg(&img[i]);
        acc += (w.x + w.y) + (w.z + w.w);
    }
    #pragma unroll
    for (int off = 16; off > 0; off >>= 1)
        acc += __shfl_xor_sync(0xFFFFFFFFu, acc, off);

    __shared__ float ws[32];
    const int lane = threadIdx.x & 31;
    const int wid  = threadIdx.x >> 5;
    if (lane == 0) ws[wid] = acc;
    __syncthreads();
    if (wid == 0) {
        const int nwarps = (blockDim.x + 31) >> 5;
        float t = (lane < nwarps) ? ws[lane] : 0.0f;
        #pragma unroll
        for (int off = 16; off > 0; off >>= 1)
            t += __shfl_xor_sync(0xFFFFFFFFu, t, off);
        if (lane == 0) g_part[b * MEAN_CHUNKS_G + chunk] = t;
    }
}

__global__ void apply_generic(const float4* __restrict__ x,
                              const int* __restrict__ sample,
                              const int* __restrict__ apply_mask,
                              float4* __restrict__ out,
                              int vec_per_img)
{
    const int b = blockIdx.y;
    const int i = blockIdx.x * blockDim.x + threadIdx.x;

    const int s  = __ldg(&sample[b]);
    const int tf = s / MAGS_PER_TF;
    const float mag = (float)(s % MAGS_PER_TF + 1) * 0.1f;
    const bool applied = (__ldg(&apply_mask[s]) > 0);

    float alpha = 1.0f, beta = 0.0f;
    if (applied) {
        if (tf == 0) { beta = mag; }
        else if (tf == 1) {
            float sum = 0.0f;
            #pragma unroll
            for (int c = 0; c < MEAN_CHUNKS_G; c++)
                sum += __ldg(&g_part[b * MEAN_CHUNKS_G + c]);
            alpha = 1.0f + mag;
            beta  = -(sum / (float)(vec_per_img * 4)) * mag;
        }
        else if (tf == 2) { alpha = 1.0f - 2.0f * mag; beta = mag; }
        else              { alpha = 1.0f + mag; }
    }

    if (i < vec_per_img) {
        const size_t idx = (size_t)b * vec_per_img + i;
        float4 w = __ldcs(&x[idx]);
        w.x = __saturatef(fmaf(alpha, w.x, beta));
        w.y = __saturatef(fmaf(alpha, w.y, beta));
        w.z = __saturatef(fmaf(alpha, w.z, beta));
        w.w = __saturatef(fmaf(alpha, w.w, beta));
        __stcs(&out[idx], w);
    }
}

// ---------------------------------------------------------------------------
extern "C" void kernel_launch(void* const* d_in, const int* in_sizes, int n_in,
                              void* d_out, int out_size)
{
    const float* x          = (const float*)d_in[0];
    const int*   sample     = (const int*)d_in[1];
    const int*   apply_mask = (const int*)d_in[2];
    float*       out        = (float*)d_out;

    const int B = in_sizes[1];                 // 256
    const int elems_per_img = in_sizes[0] / B; // 150528
    const int vec_per_img = elems_per_img / 4; // 37632

    const int tile = THREADS * VPT;            // 768
    if ((elems_per_img % 4 == 0) && (vec_per_img % tile == 0) &&
        (vec_per_img % MEAN_CHUNKS_F == 0) && B <= MAX_B) {
        const int blocks_per_img = vec_per_img / tile;   // 49
        const int grid = B * MEAN_CHUNKS_F + B * blocks_per_img;
        fused_kernel<<<grid, THREADS>>>(
            (const float4*)x, sample, apply_mask, (float4*)out,
            blocks_per_img, vec_per_img, B);
    } else {
        dim3 mgrid(B, MEAN_CHUNKS_G);
        mean_kernel<<<mgrid, 256>>>((const float4*)x, sample, apply_mask, vec_per_img);
        dim3 grid((vec_per_img + 255) / 256, B);
        apply_generic<<<grid, 256>>>((const float4*)x, sample, apply_mask,
                                     (float4*)out, vec_per_img);
    }
}

// round 16
// speedup vs baseline: 1.0484x; 1.0484x over previous
#include <cuda_runtime.h>

#define MAX_B        1024
#define MAGS_PER_TF  9
#define THREADS      128
#define VPT          6       // 128*6*49 = 37632 exact
#define NWARPS       (THREADS / 32)
#define MEAN_CHUNKS_F 6      // 37632/6 = 6272 = 128*49 -> exact reducer loop

// Persistent device state, zero-initialized at module load. All counters are
// monotonic across graph replays — no reset kernel is ever needed.
__device__ unsigned int          g_mdone[MAX_B];  // reducer-block completions
__device__ unsigned int          g_acnt[MAX_B];   // apply-block epoch counter
__device__ float                 g_sum[MAX_B];    // running sum (reset via atomicExch)
__device__ volatile unsigned int g_flag[MAX_B];   // published epoch number
__device__ volatile float        g_mean[MAX_B];   // published mean

// Generic (non-exact-tiling) fallback path scratch:
#define MEAN_CHUNKS_G 32
__device__ float g_part[MAX_B * MEAN_CHUNKS_G];

// ---------------------------------------------------------------------------
__device__ __forceinline__ float block_reduce(float val)
{
    #pragma unroll
    for (int off = 16; off > 0; off >>= 1)
        val += __shfl_xor_sync(0xFFFFFFFFu, val, off);

    __shared__ float ws[NWARPS];
    const int lane = threadIdx.x & 31;
    const int wid  = threadIdx.x >> 5;
    if (lane == 0) ws[wid] = val;
    __syncthreads();

    float v = 0.0f;
    if (wid == 0) {
        v = (lane < NWARPS) ? ws[lane] : 0.0f;
        #pragma unroll
        for (int off = 2; off > 0; off >>= 1)
            v += __shfl_xor_sync(0xFFFFFFFFu, v, off);
    }
    return v;  // valid in warp 0
}

// ---------------------------------------------------------------------------
// Fused kernel (128-thread / VPT-6 apply tiles). Grid layout:
//   [0, B*MEAN_CHUNKS_F)        front reducer blocks (contrast images only)
//   [front, front + B*bpi)      apply blocks, bpi per image, exact tiling
// Front blocks run first (in-order CTA placement): apply blocks for contrast
// images normally find the mean already published — no spin in practice.
// ---------------------------------------------------------------------------
__global__ void __launch_bounds__(THREADS)
fused_kernel(const float4* __restrict__ x,
             const int* __restrict__ sample,
             const int* __restrict__ apply_mask,
             float4* __restrict__ out,
             int blocks_per_img,
             int vec_per_img,
             int B)
{
    const int front = B * MEAN_CHUNKS_F;
    const float inv_n = 1.0f / (float)(vec_per_img * 4);

    if (blockIdx.x < front) {
        // ================= front reducer block =================
        const int b     = blockIdx.x / MEAN_CHUNKS_F;
        const int chunk = blockIdx.x - b * MEAN_CHUNKS_F;

        const int s  = __ldg(&sample[b]);
        const int tf = s / MAGS_PER_TF;
        if (!((tf == 1) && (__ldg(&apply_mask[s]) > 0))) return;  // no read

        const int chunk_vecs = vec_per_img / MEAN_CHUNKS_F;   // exact by launch check
        const unsigned int start = (unsigned int)b * vec_per_img + chunk * chunk_vecs;

        float acc = 0.0f;
        for (int i = threadIdx.x; i < chunk_vecs; i += THREADS) {
            float4 w = __ldg(&x[start + i]);   // cached: warm for the apply pass
            acc += (w.x + w.y) + (w.z + w.w);
        }
        float total = block_reduce(acc);

        if (threadIdx.x == 0) {
            atomicAdd(&g_sum[b], total);
            __threadfence();
            const unsigned int d = atomicAdd(&g_mdone[b], 1u) + 1u;
            if (d % (unsigned int)MEAN_CHUNKS_F == 0u) {
                float sum = atomicExch(&g_sum[b], 0.0f);
                g_mean[b] = sum * inv_n;
                __threadfence();
                g_flag[b] = d / (unsigned int)MEAN_CHUNKS_F;  // publish epoch
            }
        }
        return;
    }

    // ================= apply block =================
    const int abix = blockIdx.x - front;
    const int b    = abix / blocks_per_img;
    const int blk  = abix - b * blocks_per_img;

    const int s  = __ldg(&sample[b]);
    const int tf = s / MAGS_PER_TF;
    const float mag = (float)(s % MAGS_PER_TF + 1) * 0.1f;
    const bool applied  = (__ldg(&apply_mask[s]) > 0);
    const bool contrast = applied && (tf == 1);

    const unsigned int base = (unsigned int)b * (unsigned int)vec_per_img
                            + (unsigned int)blk * (THREADS * VPT)
                            + threadIdx.x;

    if (!contrast) {
        // ---------- slim streaming path (7/8 of blocks) ----------
        float alpha = 1.0f, beta = 0.0f;
        if (applied) {
            if (tf == 0)      { beta = mag; }                            // brightness
            else if (tf == 2) { alpha = 1.0f - 2.0f * mag; beta = mag; } // invert
            else              { alpha = 1.0f + mag; }                    // gain
        }

        float4 v[VPT];
        #pragma unroll
        for (int k = 0; k < VPT; k++)
            v[k] = __ldcs(&x[base + k * THREADS]);

        #pragma unroll
        for (int k = 0; k < VPT; k++) {
            v[k].x = __saturatef(fmaf(alpha, v[k].x, beta));
            v[k].y = __saturatef(fmaf(alpha, v[k].y, beta));
            v[k].z = __saturatef(fmaf(alpha, v[k].z, beta));
            v[k].w = __saturatef(fmaf(alpha, v[k].w, beta));
            __stcs(&out[base + k * THREADS], v[k]);
        }
        return;
    }

    // ---------- contrast path: mean normally already published ----------
    __shared__ float s_mean;
    __shared__ int   s_fallback;

    if (threadIdx.x == 0) {
        s_fallback = 0;
        const unsigned int d = atomicAdd(&g_acnt[b], 1u) + 1u;
        const unsigned int bp = (unsigned int)blocks_per_img;
        const unsigned int my_epoch = (d + bp - 1u) / bp;

        int spins = 0;
        while (g_flag[b] < my_epoch) {          // expected: already satisfied
            __nanosleep(40);
            if (++spins > 4000000) { s_fallback = 1; break; }
        }
        if (!s_fallback) {
            __threadfence();                     // acquire
            s_mean = g_mean[b];
        }
    }
    __syncthreads();

    if (s_fallback) {
        // Guaranteed forward progress (never expected): recompute locally.
        const float4* img = x + (size_t)b * vec_per_img;
        float a2 = 0.0f;
        for (int i = threadIdx.x; i < vec_per_img; i += THREADS) {
            float4 w = __ldg(&img[i]);
            a2 += (w.x + w.y) + (w.z + w.w);
        }
        __syncthreads();
        float t2 = block_reduce(a2);
        if (threadIdx.x == 0) s_mean = t2 * inv_n;
        __syncthreads();
    }

    const float alpha = 1.0f + mag;
    const float beta  = -s_mean * mag;

    // Single pass: data is L2-warm from the reducer blocks.
    float4 v[VPT];
    #pragma unroll
    for (int k = 0; k < VPT; k++)
        v[k] = __ldg(&x[base + k * THREADS]);

    #pragma unroll
    for (int k = 0; k < VPT; k++) {
        v[k].x = __saturatef(fmaf(alpha, v[k].x, beta));
        v[k].y = __saturatef(fmaf(alpha, v[k].y, beta));
        v[k].z = __saturatef(fmaf(alpha, v[k].z, beta));
        v[k].w = __saturatef(fmaf(alpha, v[k].w, beta));
        __stcs(&out[base + k * THREADS], v[k]);
    }
}

// ---------------------------------------------------------------------------
// Generic fallback (shapes without exact tiling): two-kernel scheme.
// ---------------------------------------------------------------------------
__global__ void mean_kernel(const float4* __restrict__ x,
                            const int* __restrict__ sample,
                            const int* __restrict__ apply_mask,
                            int vec_per_img)
{
    const int b     = blockIdx.x;
    const int chunk = blockIdx.y;

    const int s  = __ldg(&sample[b]);
    const int tf = s / MAGS_PER_TF;
    if (!((tf == 1) && (__ldg(&apply_mask[s]) > 0))) return;

    const int chunk_vecs = (vec_per_img + MEAN_CHUNKS_G - 1) / MEAN_CHUNKS_G;
    const int start = chunk * chunk_vecs;
    const int end   = min(start + chunk_vecs, vec_per_img);

    const float4* img = x + (size_t)b * vec_per_img;
    float acc = 0.0f;
    for (int i = start + threadIdx.x; i < end; i += blockDim.x) {
        float4 w = __ldg(&img[i]);
        acc += (w.x + w.y) + (w.z + w.w);
    }
    #pragma unroll
    for (int off = 16; off > 0; off >>= 1)
        acc += __shfl_xor_sync(0xFFFFFFFFu, acc, off);

    __shared__ float ws[32];
    const int lane = threadIdx.x & 31;
    const int wid  = threadIdx.x >> 5;
    if (lane == 0) ws[wid] = acc;
    __syncthreads();
    if (wid == 0) {
        const int nwarps = (blockDim.x + 31) >> 5;
        float t = (lane < nwarps) ? ws[lane] : 0.0f;
        #pragma unroll
        for (int off = 16; off > 0; off >>= 1)
            t += __shfl_xor_sync(0xFFFFFFFFu, t, off);
        if (lane == 0) g_part[b * MEAN_CHUNKS_G + chunk] = t;
    }
}

__global__ void apply_generic(const float4* __restrict__ x,
                              const int* __restrict__ sample,
                              const int* __restrict__ apply_mask,
                              float4* __restrict__ out,
                              int vec_per_img)
{
    const int b = blockIdx.y;
    const int i = blockIdx.x * blockDim.x + threadIdx.x;

    const int s  = __ldg(&sample[b]);
    const int tf = s / MAGS_PER_TF;
    const float mag = (float)(s % MAGS_PER_TF + 1) * 0.1f;
    const bool applied = (__ldg(&apply_mask[s]) > 0);

    float alpha = 1.0f, beta = 0.0f;
    if (applied) {
        if (tf == 0) { beta = mag; }
        else if (tf == 1) {
            float sum = 0.0f;
            #pragma unroll
            for (int c = 0; c < MEAN_CHUNKS_G; c++)
                sum += __ldg(&g_part[b * MEAN_CHUNKS_G + c]);
            alpha = 1.0f + mag;
            beta  = -(sum / (float)(vec_per_img * 4)) * mag;
        }
        else if (tf == 2) { alpha = 1.0f - 2.0f * mag; beta = mag; }
        else              { alpha = 1.0f + mag; }
    }

    if (i < vec_per_img) {
        const size_t idx = (size_t)b * vec_per_img + i;
        float4 w = __ldcs(&x[idx]);
        w.x = __saturatef(fmaf(alpha, w.x, beta));
        w.y = __saturatef(fmaf(alpha, w.y, beta));
        w.z = __saturatef(fmaf(alpha, w.z, beta));
        w.w = __saturatef(fmaf(alpha, w.w, beta));
        __stcs(&out[idx], w);
    }
}

// ---------------------------------------------------------------------------
extern "C" void kernel_launch(void* const* d_in, const int* in_sizes, int n_in,
                              void* d_out, int out_size)
{
    const float* x          = (const float*)d_in[0];
    const int*   sample     = (const int*)d_in[1];
    const int*   apply_mask = (const int*)d_in[2];
    float*       out        = (float*)d_out;

    const int B = in_sizes[1];                 // 256
    const int elems_per_img = in_sizes[0] / B; // 150528
    const int vec_per_img = elems_per_img / 4; // 37632

    const int tile = THREADS * VPT;            // 768
    if ((elems_per_img % 4 == 0) && (vec_per_img % tile == 0) &&
        (vec_per_img % MEAN_CHUNKS_F == 0) && B <= MAX_B) {
        const int blocks_per_img = vec_per_img / tile;   // 49
        const int grid = B * MEAN_CHUNKS_F + B * blocks_per_img;
        fused_kernel<<<grid, THREADS>>>(
            (const float4*)x, sample, apply_mask, (float4*)out,
            blocks_per_img, vec_per_img, B);
    } else {
        dim3 mgrid(B, MEAN_CHUNKS_G);
        mean_kernel<<<mgrid, 256>>>((const float4*)x, sample, apply_mask, vec_per_img);
        dim3 grid((vec_per_img + 255) / 256, B);
        apply_generic<<<grid, 256>>>((const float4*)x, sample, apply_mask,
                                     (float4*)out, vec_per_img);
    }
}